// round 12
// baseline (speedup 1.0000x reference)
#include <cuda_runtime.h>
#include <cuda_fp16.h>
#include <cstdint>

// ============================================================================
// Fused embedding-gather + GEMM, single-term fp16 on mma.sync.m16n8k16.
//   As = 32*A (fp16), Bs = 32*Wd^T (fp16);  out = (As@Bs) * 2^-10 + bd.
// R12: per-warp k-subtile phase stagger (ksr = (ks+wid+bid)&3) so warps'
//      ldsm bursts and MMA blocks interleave instead of colliding.
//      Otherwise identical to R11 (BM=BN=128, 2x2 warps of 64x64, occ 2).
// ============================================================================

#define MMAX 16384
#define KD 1024
#define ND 1024

__device__ __align__(1024) __half g_Af[(size_t)MMAX * KD];   // 32 MB, scaled x32
__device__ __align__(1024) __half g_Bf[(size_t)ND * KD];     // [n][k], scaled x32

// ---------------- helpers ----------------
__device__ __forceinline__ uint32_t s2u(const void* p) {
    uint32_t a;
    asm("{ .reg .u64 t; cvta.to.shared.u64 t, %1; cvt.u32.u64 %0, t; }" : "=r"(a) : "l"(p));
    return a;
}
__device__ __forceinline__ uint32_t swz(uint32_t o) { return o ^ ((o >> 3) & 0x70); }

__device__ __forceinline__ void cpa16(uint32_t s, const void* g) {
    asm volatile("cp.async.cg.shared.global [%0], [%1], 16;" :: "r"(s), "l"(g));
}
#define CP_COMMIT() asm volatile("cp.async.commit_group;" ::: "memory")
#define CP_WAIT1()  asm volatile("cp.async.wait_group 1;" ::: "memory")

__device__ __forceinline__ void ldsm4(uint32_t& r0, uint32_t& r1, uint32_t& r2, uint32_t& r3,
                                      uint32_t addr) {
    asm volatile("ldmatrix.sync.aligned.m8n8.x4.shared.b16 {%0,%1,%2,%3}, [%4];"
                 : "=r"(r0), "=r"(r1), "=r"(r2), "=r"(r3) : "r"(addr));
}
__device__ __forceinline__ void mma16816(float* c, const uint32_t* a, uint32_t b0, uint32_t b1) {
    asm volatile("mma.sync.aligned.m16n8k16.row.col.f32.f16.f16.f32 "
                 "{%0,%1,%2,%3}, {%4,%5,%6,%7}, {%8,%9}, {%0,%1,%2,%3};"
                 : "+f"(c[0]), "+f"(c[1]), "+f"(c[2]), "+f"(c[3])
                 : "r"(a[0]), "r"(a[1]), "r"(a[2]), "r"(a[3]), "r"(b0), "r"(b1));
}
__device__ __forceinline__ uint32_t packh2(float lo, float hi) {
    __half2 p(__float2half(lo), __float2half(hi));
    return *reinterpret_cast<uint32_t*>(&p);
}

// ---------------- merged prep: A gather/split + B transpose ----------------
__global__ void build_kernel(const int4* __restrict__ x4, const float4* __restrict__ We,
                             const float4* __restrict__ be, const float* __restrict__ Wd,
                             int nablk, int total4) {
    int tid = threadIdx.x;
    if ((int)blockIdx.x < nablk) {
        int idx = blockIdx.x * 256 + tid;
        if (idx >= total4) return;
        float4 b = *be;
        int4 xv = x4[idx];
        float4 e0 = We[xv.x], e1 = We[xv.y], e2 = We[xv.z], e3 = We[xv.w];
        uint4 p0, p1;
        p0.x = packh2(32.f * (e0.x + b.x), 32.f * (e0.y + b.y));
        p0.y = packh2(32.f * (e0.z + b.z), 32.f * (e0.w + b.w));
        p0.z = packh2(32.f * (e1.x + b.x), 32.f * (e1.y + b.y));
        p0.w = packh2(32.f * (e1.z + b.z), 32.f * (e1.w + b.w));
        p1.x = packh2(32.f * (e2.x + b.x), 32.f * (e2.y + b.y));
        p1.y = packh2(32.f * (e2.z + b.z), 32.f * (e2.w + b.w));
        p1.z = packh2(32.f * (e3.x + b.x), 32.f * (e3.y + b.y));
        p1.w = packh2(32.f * (e3.z + b.z), 32.f * (e3.w + b.w));
        uint4* dst = reinterpret_cast<uint4*>(g_Af);
        dst[idx * 2 + 0] = p0;
        dst[idx * 2 + 1] = p1;
    } else {
        __shared__ float t[32][33];
        int bid = blockIdx.x - nablk;
        int n0 = (bid & 31) * 32, k0 = (bid >> 5) * 32;
        int tx = tid & 31, ty = tid >> 5;   // 32 x 8
#pragma unroll
        for (int r = 0; r < 4; r++)
            t[ty + 8 * r][tx] = Wd[(size_t)(k0 + ty + 8 * r) * ND + n0 + tx];
        __syncthreads();
#pragma unroll
        for (int r = 0; r < 4; r++) {
            int n = n0 + ty + 8 * r, k = k0 + tx;
            g_Bf[(size_t)n * KD + k] = __float2half(32.f * t[tx][ty + 8 * r]);
        }
    }
}

// ---------------- GEMM: BM=BN=128, 4 warps of 64x64, occ 2 ------------------
#define BM 128
#define BN 128
#define BK 64
#define NT (KD / BK)              // 16 k-tiles
#define SM_A  0
#define SM_B  16384
#define STAGE_BYTES 32768         // A 16K + B 16K
#define DYN_SMEM (3 * STAGE_BYTES)

extern __shared__ __align__(1024) uint8_t smem[];

__device__ __forceinline__ void load_tiles(int tile, int stage, int m0, int n0, int tid) {
    uint32_t sb = s2u(smem) + stage * STAGE_BYTES;
    int k0 = tile * BK;
    const char* af = (const char*)g_Af;
    const char* bf = (const char*)g_Bf;
#pragma unroll
    for (int q = 0; q < 8; q++) {              // 128 rows x 8 chunks, 128 thr
        int cid = q * 128 + tid;
        int r = cid >> 3, c = cid & 7;
        uint32_t so = swz(r * 128 + c * 16);
        cpa16(sb + SM_A + so, af + ((size_t)(m0 + r) * KD + k0 + c * 8) * 2);
        cpa16(sb + SM_B + so, bf + ((size_t)(n0 + r) * KD + k0 + c * 8) * 2);
    }
}

__global__ __launch_bounds__(128, 2)
void gemm_kernel(const float* __restrict__ bd, float* __restrict__ out) {
    const int tid = threadIdx.x, lane = tid & 31, wid = tid >> 5;
    const int m0 = blockIdx.y * BM, n0 = blockIdx.x * BN;
    const int wm = (wid >> 1) * 64;            // 2 x 2 warp grid, 64x64 each
    const int wn = (wid & 1) * 64;
    const uint32_t sbase = s2u(smem);
    const int kphase = (wid + blockIdx.x) & 3; // per-warp k-subtile phase offset

    const int lrow = (lane & 7) + ((lane >> 3) & 1) * 8;
    const int lcol = (lane >> 4) * 16;

    float c[4][8][4];
#pragma unroll
    for (int i = 0; i < 4; i++)
#pragma unroll
        for (int j = 0; j < 8; j++)
#pragma unroll
            for (int v = 0; v < 4; v++) c[i][j][v] = 0.f;

    load_tiles(0, 0, m0, n0, tid); CP_COMMIT();
    load_tiles(1, 1, m0, n0, tid); CP_COMMIT();

    for (int it = 0; it < NT; it++) {
        CP_WAIT1();                            // tile it resident
        __syncthreads();                       // all reads of tile it-1 done
        if (it + 2 < NT) load_tiles(it + 2, (it + 2) % 3, m0, n0, tid);
        CP_COMMIT();

        uint32_t sb = sbase + (it % 3) * STAGE_BYTES;
#pragma unroll
        for (int ks = 0; ks < 4; ks++) {       // staggered order per warp
            const int ksr = (ks + kphase) & 3;
            uint32_t af[4][4], bfr[8][2];
#pragma unroll
            for (int i = 0; i < 4; i++) {
                uint32_t off = swz((wm + i * 16 + lrow) * 128 + ksr * 32 + lcol);
                ldsm4(af[i][0], af[i][1], af[i][2], af[i][3], sb + SM_A + off);
            }
#pragma unroll
            for (int j2 = 0; j2 < 4; j2++) {
                uint32_t off = swz((wn + j2 * 16 + lrow) * 128 + ksr * 32 + lcol);
                uint32_t r0, r1, r2, r3;
                ldsm4(r0, r1, r2, r3, sb + SM_B + off);
                bfr[j2 * 2][0] = r0; bfr[j2 * 2][1] = r2;
                bfr[j2 * 2 + 1][0] = r1; bfr[j2 * 2 + 1][1] = r3;
            }
#pragma unroll
            for (int i = 0; i < 4; i++)
#pragma unroll
                for (int j = 0; j < 8; j++)
                    mma16816(c[i][j], af[i], bfr[j][0], bfr[j][1]);
        }
    }

    // ---- epilogue: unscale (2^-10), add bias, direct stores ----
    const float SCL = 1.0f / 1024.0f;
    const int gcol0 = n0 + wn + (lane & 3) * 2;
    const int grow0 = m0 + wm + (lane >> 2);
#pragma unroll
    for (int j = 0; j < 8; j++) {
        int colg = gcol0 + j * 8;
        float2 bb = *(const float2*)&bd[colg];
#pragma unroll
        for (int i = 0; i < 4; i++) {
            int r0 = grow0 + i * 16;
            float2 o0 = make_float2(c[i][j][0] * SCL + bb.x, c[i][j][1] * SCL + bb.y);
            float2 o1 = make_float2(c[i][j][2] * SCL + bb.x, c[i][j][3] * SCL + bb.y);
            *(float2*)&out[(size_t)r0 * ND + colg]       = o0;
            *(float2*)&out[(size_t)(r0 + 8) * ND + colg] = o1;
        }
    }
}

// ---------------- launch ----------------
extern "C" void kernel_launch(void* const* d_in, const int* in_sizes, int n_in,
                              void* d_out, int out_size) {
    const int*    x    = (const int*)d_in[0];
    const float4* We   = (const float4*)d_in[1];
    const float4* be   = (const float4*)d_in[2];
    const float*  Wd   = (const float*)d_in[3];
    const float*  bd   = (const float*)d_in[4];
    float*        out  = (float*)d_out;

    int total = in_sizes[0];                   // B*256
    int M = total / 256;
    int total4 = total / 4;
    int nablk = (total4 + 255) / 256;          // 4096

    build_kernel<<<nablk + 1024, 256>>>((const int4*)x, We, be, Wd, nablk, total4);

    static int attr_done = 0;
    if (!attr_done) {
        cudaFuncSetAttribute(gemm_kernel, cudaFuncAttributeMaxDynamicSharedMemorySize, DYN_SMEM);
        attr_done = 1;
    }
    dim3 grid(ND / BN, M / BM);                // (8, 128)
    gemm_kernel<<<grid, 128, DYN_SMEM>>>(bd, out);
}

// round 15
// speedup vs baseline: 1.0328x; 1.0328x over previous
#include <cuda_runtime.h>
#include <cuda_fp16.h>
#include <cstdint>

// ============================================================================
// Fused embedding-gather + GEMM, single-term fp16 on mma.sync.m16n8k16.
//   As = 32*A (fp16), Bs = 32*Wd^T (fp16);  out = (As@Bs) * 2^-10 + bd.
// R15 (= R13 resubmit #2; R13/R14 hit broker-side container failures):
//   - refill cp.async inside ks=0 MMA shadow (decouple LDGSTS burst from
//     post-barrier ldsm burst)
//   - XOR-linear ldsm addressing (base ^ ks*32; swizzle is XOR-linear in ks)
//   - build_a at 8 idx/thread
//   Base: BM=BN=128, 2x2 warps of 64x64, occ 2, 3-stage cp.async ring.
// ============================================================================

#define MMAX 16384
#define KD 1024
#define ND 1024

__device__ __align__(1024) __half g_Af[(size_t)MMAX * KD];   // 32 MB, scaled x32
__device__ __align__(1024) __half g_Bf[(size_t)ND * KD];     // [n][k], scaled x32

// ---------------- helpers ----------------
__device__ __forceinline__ uint32_t s2u(const void* p) {
    uint32_t a;
    asm("{ .reg .u64 t; cvta.to.shared.u64 t, %1; cvt.u32.u64 %0, t; }" : "=r"(a) : "l"(p));
    return a;
}
__device__ __forceinline__ uint32_t swz(uint32_t o) { return o ^ ((o >> 3) & 0x70); }

__device__ __forceinline__ void cpa16(uint32_t s, const void* g) {
    asm volatile("cp.async.cg.shared.global [%0], [%1], 16;" :: "r"(s), "l"(g));
}
#define CP_COMMIT() asm volatile("cp.async.commit_group;" ::: "memory")
#define CP_WAIT1()  asm volatile("cp.async.wait_group 1;" ::: "memory")

__device__ __forceinline__ void ldsm4(uint32_t& r0, uint32_t& r1, uint32_t& r2, uint32_t& r3,
                                      uint32_t addr) {
    asm volatile("ldmatrix.sync.aligned.m8n8.x4.shared.b16 {%0,%1,%2,%3}, [%4];"
                 : "=r"(r0), "=r"(r1), "=r"(r2), "=r"(r3) : "r"(addr));
}
__device__ __forceinline__ void mma16816(float* c, const uint32_t* a, uint32_t b0, uint32_t b1) {
    asm volatile("mma.sync.aligned.m16n8k16.row.col.f32.f16.f16.f32 "
                 "{%0,%1,%2,%3}, {%4,%5,%6,%7}, {%8,%9}, {%0,%1,%2,%3};"
                 : "+f"(c[0]), "+f"(c[1]), "+f"(c[2]), "+f"(c[3])
                 : "r"(a[0]), "r"(a[1]), "r"(a[2]), "r"(a[3]), "r"(b0), "r"(b1));
}
__device__ __forceinline__ uint32_t packh2(float lo, float hi) {
    __half2 p(__float2half(lo), __float2half(hi));
    return *reinterpret_cast<uint32_t*>(&p);
}

// ---------------- merged prep: A gather (8 idx/thread) + B transpose --------
__global__ void build_kernel(const int4* __restrict__ x4, const float4* __restrict__ We,
                             const float4* __restrict__ be, const float* __restrict__ Wd,
                             int nablk, int total8) {
    int tid = threadIdx.x;
    if ((int)blockIdx.x < nablk) {
        int idx = blockIdx.x * 256 + tid;          // one idx = 8 input tokens
        if (idx >= total8) return;
        float4 b = *be;
        int4 xa = x4[idx * 2 + 0];
        int4 xb = x4[idx * 2 + 1];
        int xs[8] = {xa.x, xa.y, xa.z, xa.w, xb.x, xb.y, xb.z, xb.w};
        uint4* dst = reinterpret_cast<uint4*>(g_Af);
#pragma unroll
        for (int h = 0; h < 4; h++) {
            float4 e0 = We[xs[h * 2]], e1 = We[xs[h * 2 + 1]];
            uint4 p;
            p.x = packh2(32.f * (e0.x + b.x), 32.f * (e0.y + b.y));
            p.y = packh2(32.f * (e0.z + b.z), 32.f * (e0.w + b.w));
            p.z = packh2(32.f * (e1.x + b.x), 32.f * (e1.y + b.y));
            p.w = packh2(32.f * (e1.z + b.z), 32.f * (e1.w + b.w));
            dst[idx * 4 + h] = p;
        }
    } else {
        __shared__ float t[32][33];
        int bid = blockIdx.x - nablk;
        int n0 = (bid & 31) * 32, k0 = (bid >> 5) * 32;
        int tx = tid & 31, ty = tid >> 5;   // 32 x 8
#pragma unroll
        for (int r = 0; r < 4; r++)
            t[ty + 8 * r][tx] = Wd[(size_t)(k0 + ty + 8 * r) * ND + n0 + tx];
        __syncthreads();
#pragma unroll
        for (int r = 0; r < 4; r++) {
            int n = n0 + ty + 8 * r, k = k0 + tx;
            g_Bf[(size_t)n * KD + k] = __float2half(32.f * t[tx][ty + 8 * r]);
        }
    }
}

// ---------------- GEMM: BM=BN=128, 4 warps of 64x64, occ 2 ------------------
#define BM 128
#define BN 128
#define BK 64
#define NT (KD / BK)              // 16 k-tiles
#define SM_A  0
#define SM_B  16384
#define STAGE_BYTES 32768         // A 16K + B 16K
#define DYN_SMEM (3 * STAGE_BYTES)

extern __shared__ __align__(1024) uint8_t smem[];

__device__ __forceinline__ void load_tiles(int tile, int stage, int m0, int n0, int tid) {
    uint32_t sb = s2u(smem) + stage * STAGE_BYTES;
    int k0 = tile * BK;
    const char* af = (const char*)g_Af;
    const char* bf = (const char*)g_Bf;
#pragma unroll
    for (int q = 0; q < 8; q++) {              // 128 rows x 8 chunks, 128 thr
        int cid = q * 128 + tid;
        int r = cid >> 3, c = cid & 7;
        uint32_t so = swz(r * 128 + c * 16);
        cpa16(sb + SM_A + so, af + ((size_t)(m0 + r) * KD + k0 + c * 8) * 2);
        cpa16(sb + SM_B + so, bf + ((size_t)(n0 + r) * KD + k0 + c * 8) * 2);
    }
}

__global__ __launch_bounds__(128, 2)
void gemm_kernel(const float* __restrict__ bd, float* __restrict__ out) {
    const int tid = threadIdx.x, lane = tid & 31, wid = tid >> 5;
    const int m0 = blockIdx.y * BM, n0 = blockIdx.x * BN;
    const int wm = (wid >> 1) * 64;            // 2 x 2 warp grid, 64x64 each
    const int wn = (wid & 1) * 64;
    const uint32_t sbase = s2u(smem);
    const int kphase = (wid + blockIdx.x) & 3;

    const int lrow = (lane & 7) + ((lane >> 3) & 1) * 8;
    const int lcol = (lane >> 4) * 16;

    // XOR-linear ldsm bases: addr(ks) = stagebase + (base ^ (ksr<<5)).
    // swz scrambles bits [6:4] with row&7 (bits [9:7]); ks enters the chunk
    // field as bits [6:5] with no carries, so it composes as a pure XOR.
    uint32_t aBase[4], bBase[4];
#pragma unroll
    for (int i = 0; i < 4; i++)
        aBase[i] = SM_A + swz((wm + i * 16 + lrow) * 128 + lcol);
#pragma unroll
    for (int j2 = 0; j2 < 4; j2++)
        bBase[j2] = SM_B + swz((wn + j2 * 16 + lrow) * 128 + lcol);

    float c[4][8][4];
#pragma unroll
    for (int i = 0; i < 4; i++)
#pragma unroll
        for (int j = 0; j < 8; j++)
#pragma unroll
            for (int v = 0; v < 4; v++) c[i][j][v] = 0.f;

    load_tiles(0, 0, m0, n0, tid); CP_COMMIT();
    load_tiles(1, 1, m0, n0, tid); CP_COMMIT();

    for (int it = 0; it < NT; it++) {
        CP_WAIT1();                            // tile it resident
        __syncthreads();                       // all reads of tile it-1 done

        uint32_t sb = sbase + (it % 3) * STAGE_BYTES;
#pragma unroll
        for (int ks = 0; ks < 4; ks++) {
            const uint32_t kx = (uint32_t)(((ks + kphase) & 3) << 5);
            uint32_t af[4][4], bfr[8][2];
#pragma unroll
            for (int i = 0; i < 4; i++)
                ldsm4(af[i][0], af[i][1], af[i][2], af[i][3], sb + (aBase[i] ^ kx));
#pragma unroll
            for (int j2 = 0; j2 < 4; j2++) {
                uint32_t r0, r1, r2, r3;
                ldsm4(r0, r1, r2, r3, sb + (bBase[j2] ^ kx));
                bfr[j2 * 2][0] = r0; bfr[j2 * 2][1] = r2;
                bfr[j2 * 2 + 1][0] = r1; bfr[j2 * 2 + 1][1] = r3;
            }
#pragma unroll
            for (int i = 0; i < 4; i++)
#pragma unroll
                for (int j = 0; j < 8; j++)
                    mma16816(c[i][j], af[i], bfr[j][0], bfr[j][1]);
            // Refill in the MMA shadow of ks=0: tensor pipe grinds ~32 MMAs
            // while the LDGSTS burst drains through MIO, instead of colliding
            // with every warp's post-barrier ldsm burst.
            if (ks == 0 && it + 2 < NT) {
                load_tiles(it + 2, (it + 2) % 3, m0, n0, tid);
                CP_COMMIT();
            }
        }
    }

    // ---- epilogue: unscale (2^-10), add bias, direct stores ----
    const float SCL = 1.0f / 1024.0f;
    const int gcol0 = n0 + wn + (lane & 3) * 2;
    const int grow0 = m0 + wm + (lane >> 2);
#pragma unroll
    for (int j = 0; j < 8; j++) {
        int colg = gcol0 + j * 8;
        float2 bb = *(const float2*)&bd[colg];
#pragma unroll
        for (int i = 0; i < 4; i++) {
            int r0 = grow0 + i * 16;
            float2 o0 = make_float2(c[i][j][0] * SCL + bb.x, c[i][j][1] * SCL + bb.y);
            float2 o1 = make_float2(c[i][j][2] * SCL + bb.x, c[i][j][3] * SCL + bb.y);
            *(float2*)&out[(size_t)r0 * ND + colg]       = o0;
            *(float2*)&out[(size_t)(r0 + 8) * ND + colg] = o1;
        }
    }
}

// ---------------- launch ----------------
extern "C" void kernel_launch(void* const* d_in, const int* in_sizes, int n_in,
                              void* d_out, int out_size) {
    const int*    x    = (const int*)d_in[0];
    const float4* We   = (const float4*)d_in[1];
    const float4* be   = (const float4*)d_in[2];
    const float*  Wd   = (const float*)d_in[3];
    const float*  bd   = (const float*)d_in[4];
    float*        out  = (float*)d_out;

    int total = in_sizes[0];                   // B*256
    int M = total / 256;
    int total8 = total / 8;
    int nablk = (total8 + 255) / 256;          // 2048

    build_kernel<<<nablk + 1024, 256>>>((const int4*)x, We, be, Wd, nablk, total8);

    static int attr_done = 0;
    if (!attr_done) {
        cudaFuncSetAttribute(gemm_kernel, cudaFuncAttributeMaxDynamicSharedMemorySize, DYN_SMEM);
        attr_done = 1;
    }
    dim3 grid(ND / BN, M / BM);                // (8, 128)
    gemm_kernel<<<grid, 128, DYN_SMEM>>>(bd, out);
}

// round 16
// speedup vs baseline: 1.0554x; 1.0219x over previous
#include <cuda_runtime.h>
#include <cuda_fp16.h>
#include <cstdint>

// ============================================================================
// Fused embedding-gather + GEMM, single-term fp16 on mma.sync.m16n8k16.
//   As = 32*A (fp16), Bs = 32*Wd^T (fp16);  out = (As@Bs) * 2^-10 + bd.
// R16: retile BM=64 x BN=128, 128-thread CTAs (2x2 warps of 32x64), occ 3
//      (3 warps/SMSP for latency cover) and 2048 CTAs (tail 13.5% -> 7.8%).
//      Keeps: 3-stage cp.async ring, ks0-shadow refill, XOR-linear ldsm.
// ============================================================================

#define MMAX 16384
#define KD 1024
#define ND 1024

__device__ __align__(1024) __half g_Af[(size_t)MMAX * KD];   // 32 MB, scaled x32
__device__ __align__(1024) __half g_Bf[(size_t)ND * KD];     // [n][k], scaled x32

// ---------------- helpers ----------------
__device__ __forceinline__ uint32_t s2u(const void* p) {
    uint32_t a;
    asm("{ .reg .u64 t; cvta.to.shared.u64 t, %1; cvt.u32.u64 %0, t; }" : "=r"(a) : "l"(p));
    return a;
}
__device__ __forceinline__ uint32_t swz(uint32_t o) { return o ^ ((o >> 3) & 0x70); }

__device__ __forceinline__ void cpa16(uint32_t s, const void* g) {
    asm volatile("cp.async.cg.shared.global [%0], [%1], 16;" :: "r"(s), "l"(g));
}
#define CP_COMMIT() asm volatile("cp.async.commit_group;" ::: "memory")
#define CP_WAIT1()  asm volatile("cp.async.wait_group 1;" ::: "memory")

__device__ __forceinline__ void ldsm4(uint32_t& r0, uint32_t& r1, uint32_t& r2, uint32_t& r3,
                                      uint32_t addr) {
    asm volatile("ldmatrix.sync.aligned.m8n8.x4.shared.b16 {%0,%1,%2,%3}, [%4];"
                 : "=r"(r0), "=r"(r1), "=r"(r2), "=r"(r3) : "r"(addr));
}
__device__ __forceinline__ void mma16816(float* c, const uint32_t* a, uint32_t b0, uint32_t b1) {
    asm volatile("mma.sync.aligned.m16n8k16.row.col.f32.f16.f16.f32 "
                 "{%0,%1,%2,%3}, {%4,%5,%6,%7}, {%8,%9}, {%0,%1,%2,%3};"
                 : "+f"(c[0]), "+f"(c[1]), "+f"(c[2]), "+f"(c[3])
                 : "r"(a[0]), "r"(a[1]), "r"(a[2]), "r"(a[3]), "r"(b0), "r"(b1));
}
__device__ __forceinline__ uint32_t packh2(float lo, float hi) {
    __half2 p(__float2half(lo), __float2half(hi));
    return *reinterpret_cast<uint32_t*>(&p);
}

// ---------------- merged prep: A gather (8 idx/thread) + B transpose --------
__global__ void build_kernel(const int4* __restrict__ x4, const float4* __restrict__ We,
                             const float4* __restrict__ be, const float* __restrict__ Wd,
                             int nablk, int total8) {
    int tid = threadIdx.x;
    if ((int)blockIdx.x < nablk) {
        int idx = blockIdx.x * 256 + tid;          // one idx = 8 input tokens
        if (idx >= total8) return;
        float4 b = *be;
        int4 xa = x4[idx * 2 + 0];
        int4 xb = x4[idx * 2 + 1];
        int xs[8] = {xa.x, xa.y, xa.z, xa.w, xb.x, xb.y, xb.z, xb.w};
        uint4* dst = reinterpret_cast<uint4*>(g_Af);
#pragma unroll
        for (int h = 0; h < 4; h++) {
            float4 e0 = We[xs[h * 2]], e1 = We[xs[h * 2 + 1]];
            uint4 p;
            p.x = packh2(32.f * (e0.x + b.x), 32.f * (e0.y + b.y));
            p.y = packh2(32.f * (e0.z + b.z), 32.f * (e0.w + b.w));
            p.z = packh2(32.f * (e1.x + b.x), 32.f * (e1.y + b.y));
            p.w = packh2(32.f * (e1.z + b.z), 32.f * (e1.w + b.w));
            dst[idx * 4 + h] = p;
        }
    } else {
        __shared__ float t[32][33];
        int bid = blockIdx.x - nablk;
        int n0 = (bid & 31) * 32, k0 = (bid >> 5) * 32;
        int tx = tid & 31, ty = tid >> 5;   // 32 x 8
#pragma unroll
        for (int r = 0; r < 4; r++)
            t[ty + 8 * r][tx] = Wd[(size_t)(k0 + ty + 8 * r) * ND + n0 + tx];
        __syncthreads();
#pragma unroll
        for (int r = 0; r < 4; r++) {
            int n = n0 + ty + 8 * r, k = k0 + tx;
            g_Bf[(size_t)n * KD + k] = __float2half(32.f * t[tx][ty + 8 * r]);
        }
    }
}

// ---------------- GEMM: BM=64 BN=128, 4 warps of 32x64, occ 3 ---------------
#define BM 64
#define BN 128
#define BK 64
#define NT (KD / BK)              // 16 k-tiles
#define SM_A  0
#define SM_B  8192
#define STAGE_BYTES 24576         // A 8K + B 16K
#define DYN_SMEM (3 * STAGE_BYTES)

extern __shared__ __align__(1024) uint8_t smem[];

__device__ __forceinline__ void load_tiles(int tile, int stage, int m0, int n0, int tid) {
    uint32_t sb = s2u(smem) + stage * STAGE_BYTES;
    int k0 = tile * BK;
    const char* af = (const char*)g_Af;
    const char* bf = (const char*)g_Bf;
#pragma unroll
    for (int q = 0; q < 4; q++) {              // A: 64 rows x 8 chunks, 128 thr
        int cid = q * 128 + tid;
        int r = cid >> 3, c = cid & 7;
        uint32_t so = swz(r * 128 + c * 16);
        cpa16(sb + SM_A + so, af + ((size_t)(m0 + r) * KD + k0 + c * 8) * 2);
    }
#pragma unroll
    for (int q = 0; q < 8; q++) {              // B: 128 rows x 8 chunks
        int cid = q * 128 + tid;
        int r = cid >> 3, c = cid & 7;
        uint32_t so = swz(r * 128 + c * 16);
        cpa16(sb + SM_B + so, bf + ((size_t)(n0 + r) * KD + k0 + c * 8) * 2);
    }
}

__global__ __launch_bounds__(128, 3)
void gemm_kernel(const float* __restrict__ bd, float* __restrict__ out) {
    const int tid = threadIdx.x, lane = tid & 31, wid = tid >> 5;
    const int m0 = blockIdx.y * BM, n0 = blockIdx.x * BN;
    const int wm = (wid >> 1) * 32;            // 2 x 2 warp grid, 32x64 each
    const int wn = (wid & 1) * 64;
    const uint32_t sbase = s2u(smem);
    const int kphase = (wid + blockIdx.x) & 3;

    const int lrow = (lane & 7) + ((lane >> 3) & 1) * 8;
    const int lcol = (lane >> 4) * 16;

    // XOR-linear ldsm bases: addr(ks) = stagebase + (base ^ (ksr<<5)).
    uint32_t aBase[2], bBase[4];
#pragma unroll
    for (int i = 0; i < 2; i++)
        aBase[i] = SM_A + swz((wm + i * 16 + lrow) * 128 + lcol);
#pragma unroll
    for (int j2 = 0; j2 < 4; j2++)
        bBase[j2] = SM_B + swz((wn + j2 * 16 + lrow) * 128 + lcol);

    float c[2][8][4];
#pragma unroll
    for (int i = 0; i < 2; i++)
#pragma unroll
        for (int j = 0; j < 8; j++)
#pragma unroll
            for (int v = 0; v < 4; v++) c[i][j][v] = 0.f;

    load_tiles(0, 0, m0, n0, tid); CP_COMMIT();
    load_tiles(1, 1, m0, n0, tid); CP_COMMIT();

    for (int it = 0; it < NT; it++) {
        CP_WAIT1();                            // tile it resident
        __syncthreads();                       // all reads of tile it-1 done

        uint32_t sb = sbase + (it % 3) * STAGE_BYTES;
#pragma unroll
        for (int ks = 0; ks < 4; ks++) {
            const uint32_t kx = (uint32_t)(((ks + kphase) & 3) << 5);
            uint32_t af[2][4], bfr[8][2];
#pragma unroll
            for (int i = 0; i < 2; i++)
                ldsm4(af[i][0], af[i][1], af[i][2], af[i][3], sb + (aBase[i] ^ kx));
#pragma unroll
            for (int j2 = 0; j2 < 4; j2++) {
                uint32_t r0, r1, r2, r3;
                ldsm4(r0, r1, r2, r3, sb + (bBase[j2] ^ kx));
                bfr[j2 * 2][0] = r0; bfr[j2 * 2][1] = r2;
                bfr[j2 * 2 + 1][0] = r1; bfr[j2 * 2 + 1][1] = r3;
            }
#pragma unroll
            for (int i = 0; i < 2; i++)
#pragma unroll
                for (int j = 0; j < 8; j++)
                    mma16816(c[i][j], af[i], bfr[j][0], bfr[j][1]);
            // Refill in the ks0 MMA shadow.
            if (ks == 0 && it + 2 < NT) {
                load_tiles(it + 2, (it + 2) % 3, m0, n0, tid);
                CP_COMMIT();
            }
        }
    }

    // ---- epilogue: unscale (2^-10), add bias, direct stores ----
    const float SCL = 1.0f / 1024.0f;
    const int gcol0 = n0 + wn + (lane & 3) * 2;
    const int grow0 = m0 + wm + (lane >> 2);
#pragma unroll
    for (int j = 0; j < 8; j++) {
        int colg = gcol0 + j * 8;
        float2 bb = *(const float2*)&bd[colg];
#pragma unroll
        for (int i = 0; i < 2; i++) {
            int r0 = grow0 + i * 16;
            float2 o0 = make_float2(c[i][j][0] * SCL + bb.x, c[i][j][1] * SCL + bb.y);
            float2 o1 = make_float2(c[i][j][2] * SCL + bb.x, c[i][j][3] * SCL + bb.y);
            *(float2*)&out[(size_t)r0 * ND + colg]       = o0;
            *(float2*)&out[(size_t)(r0 + 8) * ND + colg] = o1;
        }
    }
}

// ---------------- launch ----------------
extern "C" void kernel_launch(void* const* d_in, const int* in_sizes, int n_in,
                              void* d_out, int out_size) {
    const int*    x    = (const int*)d_in[0];
    const float4* We   = (const float4*)d_in[1];
    const float4* be   = (const float4*)d_in[2];
    const float*  Wd   = (const float*)d_in[3];
    const float*  bd   = (const float*)d_in[4];
    float*        out  = (float*)d_out;

    int total = in_sizes[0];                   // B*256
    int M = total / 256;
    int total8 = total / 8;
    int nablk = (total8 + 255) / 256;          // 2048

    build_kernel<<<nablk + 1024, 256>>>((const int4*)x, We, be, Wd, nablk, total8);

    static int attr_done = 0;
    if (!attr_done) {
        cudaFuncSetAttribute(gemm_kernel, cudaFuncAttributeMaxDynamicSharedMemorySize, DYN_SMEM);
        attr_done = 1;
    }
    dim3 grid(ND / BN, M / BM);                // (8, 256) = 2048 CTAs
    gemm_kernel<<<grid, 128, DYN_SMEM>>>(bd, out);
}